// round 3
// baseline (speedup 1.0000x reference)
#include <cuda_runtime.h>
#include <math.h>

#define B 8
#define C 512
#define N 1024
#define TOPK 12

// ---------------- device scratch (no allocations allowed) ----------------
__device__ float g_cntf[B], g_cntb[B];
__device__ float g_FP[B*C], g_BP[B*C];
__device__ float g_nFP[B], g_nBP[B];
__device__ float g_predfg[B*N], g_predbg[B*N];
__device__ float g_invn[B*N], g_qn[B*N];
__device__ float g_wf[B*N];
__device__ float g_wfsum[B];
__device__ int   g_idx[B*N];
__device__ int   g_M[B];
__device__ float g_invg[B*N];
__device__ float g_Vg[(size_t)B*C*N];        // gathered active columns of cur
__device__ float g_S[(size_t)B*N*N];         // exp scores (N x M per batch)
__device__ float g_denom[B*N];
__device__ float g_ASBP[(size_t)B*C*N];      // bg_local
__device__ float g_fgp[B*C], g_bgp[B*C];
__device__ float g_FP1[B*C];
__device__ float g_nFP1[B];

// ---------------- helpers ----------------
__device__ __forceinline__ float warp_sum(float v) {
    #pragma unroll
    for (int off = 16; off > 0; off >>= 1) v += __shfl_down_sync(0xffffffffu, v, off);
    return v;
}

// ---------------- K0: mask counts ----------------
__global__ void k_count(const int* __restrict__ mask) {
    int b = blockIdx.x, n = threadIdx.x;
    int mk = mask[b*N + n];
    int c1 = __syncthreads_count(mk == 1);
    int c0 = __syncthreads_count(mk == 0);
    if (n == 0) { g_cntf[b] = (float)c1; g_cntb[b] = (float)c0; }
}

// ---------------- K1: masked avg pool (FP/BP), one warp per (b,c) ----------------
__global__ void k_pool(const float* __restrict__ sf, const int* __restrict__ mask) {
    int w = blockIdx.x * 8 + (threadIdx.x >> 5);
    int lane = threadIdx.x & 31;
    int b = w / C, c = w % C;
    const float* row = sf + ((size_t)b*C + c)*N;
    const int* mrow = mask + b*N;
    float s1 = 0.f, s0 = 0.f;
    for (int n = lane; n < N; n += 32) {
        float v = row[n];
        if (mrow[n] == 1) s1 += v; else s0 += v;
    }
    s1 = warp_sum(s1); s0 = warp_sum(s0);
    if (lane == 0) {
        g_FP[b*C + c] = s1 / (g_cntf[b] + 1e-5f);
        g_BP[b*C + c] = s0 / (g_cntb[b] + 1e-5f);
    }
}

// ---------------- K1b: proto norms ----------------
__global__ void k_norms() {
    __shared__ float sh[512];
    int b = blockIdx.x, t = threadIdx.x;
    float f = g_FP[b*C + t];
    sh[t] = f*f; __syncthreads();
    for (int off = 256; off > 0; off >>= 1) { if (t < off) sh[t] += sh[t+off]; __syncthreads(); }
    if (t == 0) g_nFP[b] = sqrtf(sh[0]);
    __syncthreads();
    float p = g_BP[b*C + t];
    sh[t] = p*p; __syncthreads();
    for (int off = 256; off > 0; off >>= 1) { if (t < off) sh[t] += sh[t+off]; __syncthreads(); }
    if (t == 0) g_nBP[b] = sqrtf(sh[0]);
}

// ---------------- K2: similarity + 2-class softmax -> pred, per-pixel norms ----------------
__global__ void k_pred(const float* __restrict__ q) {
    int g = blockIdx.x * blockDim.x + threadIdx.x;
    int b = g / N, n = g % N;
    const float* qb = q + (size_t)b*C*N + n;
    const float* fp = g_FP + b*C;
    const float* bp = g_BP + b*C;
    float df = 0.f, db = 0.f, qq = 0.f;
    for (int c = 0; c < C; c++) {
        float v = qb[(size_t)c*N];
        df += v * fp[c];
        db += v * bp[c];
        qq += v * v;
    }
    float nq = sqrtf(qq);
    float sf = 10.f * df / fmaxf(nq * g_nFP[b], 1e-8f);
    float sb = 10.f * db / fmaxf(nq * g_nBP[b], 1e-8f);
    float mx = fmaxf(sf, sb);
    float ef = expf(sf - mx), eb = expf(sb - mx);
    float inv = 1.f / (ef + eb);
    g_predfg[g] = ef * inv;
    g_predbg[g] = eb * inv;
    g_qn[g] = nq;
    g_invn[g] = 1.f / fmaxf(nq, 1e-20f);
}

// ---------------- K3: threshold / top-12 weight selection (+ bg compaction) ----------------
__global__ void k_weights() {
    int which = blockIdx.x;   // 0 = fg, 1 = bg
    int b = blockIdx.y;
    int tid = threadIdx.x;
    const float* pred = which ? (g_predbg + b*N) : (g_predfg + b*N);
    float thres = which ? 0.6f : 0.7f;
    float p = pred[tid];
    int flag = (p > thres) ? 1 : 0;
    int cnt = __syncthreads_count(flag);
    bool sel = false;
    if (cnt > 0) {
        sel = (flag != 0);
    } else {
        __shared__ float kv[1024];
        __shared__ int   ki[1024];
        bool taken = false;
        for (int t = 0; t < TOPK; t++) {
            kv[tid] = taken ? -1e30f : p;
            ki[tid] = tid;
            __syncthreads();
            for (int off = 512; off > 0; off >>= 1) {
                if (tid < off) {
                    float v2 = kv[tid+off]; int i2 = ki[tid+off];
                    if (v2 > kv[tid] || (v2 == kv[tid] && i2 < ki[tid])) { kv[tid] = v2; ki[tid] = i2; }
                }
                __syncthreads();
            }
            int win = ki[0];
            __syncthreads();
            if (tid == win) taken = true;
        }
        sel = taken;
    }
    float wsum = (cnt > 0) ? (float)cnt : (float)TOPK;
    if (which == 0) {
        g_wf[b*N + tid] = sel ? 1.f : 0.f;
        if (tid == 0) g_wfsum[b] = wsum;
    } else {
        __shared__ int ps[1024];
        int f = sel ? 1 : 0;
        ps[tid] = f; __syncthreads();
        for (int off = 1; off < 1024; off <<= 1) {
            int v = (tid >= off) ? ps[tid - off] : 0;
            __syncthreads();
            ps[tid] += v;
            __syncthreads();
        }
        if (f) {
            int pos = ps[tid] - 1;
            g_idx[b*N + pos]  = tid;
            g_invg[b*N + pos] = g_invn[b*N + tid];
        }
        if (tid == 1023) g_M[b] = ps[1023];
    }
}

// ---------------- K3b: gather active columns -> Vg, and bg_proto ----------------
__global__ void k_gather(const float* __restrict__ q) {
    int bc = blockIdx.x;
    int b = bc / C;
    int Mb = g_M[b];
    const int* idx = g_idx + b*N;
    const float* row = q + (size_t)bc*N;
    float* vrow = g_Vg + (size_t)bc*N;
    float s = 0.f;
    for (int m = threadIdx.x; m < Mb; m += blockDim.x) {
        float v = row[idx[m]];
        vrow[m] = v;
        s += v;
    }
    __shared__ float sh[128];
    int t = threadIdx.x;
    sh[t] = s; __syncthreads();
    for (int off = 64; off > 0; off >>= 1) { if (t < off) sh[t] += sh[t+off]; __syncthreads(); }
    if (t == 0) g_bgp[bc] = sh[0] / (float)Mb;
}

// ---------------- K4: fg proto, one warp per (b,c) ----------------
__global__ void k_fgproto(const float* __restrict__ q) {
    int w = blockIdx.x * 8 + (threadIdx.x >> 5);
    int lane = threadIdx.x & 31;
    int b = w / C;
    const float* row = q + (size_t)w*N;
    const float* wf = g_wf + b*N;
    float s = 0.f;
    for (int n = lane; n < N; n += 32) s += row[n] * wf[n];
    s = warp_sum(s);
    if (lane == 0) g_fgp[w] = s / g_wfsum[b];
}

// ---------------- K4b: FP1 and its norm ----------------
__global__ void k_fp1() {
    __shared__ float sh[512];
    int b = blockIdx.x, t = threadIdx.x;
    int i = b*C + t;
    float v = 0.5f * (g_FP[i] + g_fgp[i]);
    g_FP1[i] = v;
    sh[t] = v*v; __syncthreads();
    for (int off = 256; off > 0; off >>= 1) { if (t < off) sh[t] += sh[t+off]; __syncthreads(); }
    if (t == 0) g_nFP1[b] = sqrtf(sh[0]);
}

// ---------------- K5: S[i,m] = exp(2 * cn_i . cn_j(m)), 64x64 tile GEMM ----------------
__global__ __launch_bounds__(256) void k5_gemmS(const float* __restrict__ q) {
    int b  = blockIdx.z;
    int i0 = blockIdx.y * 64;
    int m0 = blockIdx.x * 64;
    int Mb = g_M[b];
    if (m0 >= Mb) return;
    __shared__ float As[16][64];
    __shared__ float Bs[16][64];
    int tx = threadIdx.x & 15, ty = threadIdx.x >> 4;
    float acc[4][4] = {};
    const float* qb = q + (size_t)b*C*N;
    const float* vg = g_Vg + (size_t)b*C*N;
    int t = threadIdx.x;
    int kk_l = t >> 4;            // 0..15
    int col_l = (t & 15) * 4;     // 0..60
    for (int k0 = 0; k0 < C; k0 += 16) {
        float4 va = *(const float4*)(qb + (size_t)(k0 + kk_l)*N + i0 + col_l);
        *(float4*)&As[kk_l][col_l] = va;
        float4 vb = *(const float4*)(vg + (size_t)(k0 + kk_l)*N + m0 + col_l);
        *(float4*)&Bs[kk_l][col_l] = vb;
        __syncthreads();
        #pragma unroll
        for (int kk = 0; kk < 16; kk++) {
            float4 fa = *(const float4*)&As[kk][ty*4];
            float4 fb = *(const float4*)&Bs[kk][tx*4];
            float a0 = fa.x, a1 = fa.y, a2 = fa.z, a3 = fa.w;
            float b0 = fb.x, b1 = fb.y, b2 = fb.z, b3 = fb.w;
            acc[0][0] += a0*b0; acc[0][1] += a0*b1; acc[0][2] += a0*b2; acc[0][3] += a0*b3;
            acc[1][0] += a1*b0; acc[1][1] += a1*b1; acc[1][2] += a1*b2; acc[1][3] += a1*b3;
            acc[2][0] += a2*b0; acc[2][1] += a2*b1; acc[2][2] += a2*b2; acc[2][3] += a2*b3;
            acc[3][0] += a3*b0; acc[3][1] += a3*b1; acc[3][2] += a3*b2; acc[3][3] += a3*b3;
        }
        __syncthreads();
    }
    float invi[4];
    #pragma unroll
    for (int r = 0; r < 4; r++) invi[r] = g_invn[b*N + i0 + ty*4 + r];
    #pragma unroll
    for (int cI = 0; cI < 4; cI++) {
        int m = m0 + tx*4 + cI;
        if (m < Mb) {
            float invj = g_invg[b*N + m];
            #pragma unroll
            for (int r = 0; r < 4; r++) {
                g_S[((size_t)b*N + i0 + ty*4 + r)*N + m] = __expf(2.f * acc[r][cI] * invi[r] * invj);
            }
        }
    }
}

// ---------------- K6: row sums (softmax denominator) ----------------
__global__ void k_denom() {
    int w = blockIdx.x * 8 + (threadIdx.x >> 5);
    int lane = threadIdx.x & 31;
    int b = w / N, i = w % N;
    int Mb = g_M[b];
    const float* srow = g_S + ((size_t)b*N + i)*N;
    float s = 0.f;
    for (int m = lane; m < Mb; m += 32) s += srow[m];
    s = warp_sum(s);
    if (lane == 0) g_denom[w] = s;
}

// ---------------- K7: ASBP = (Vg @ S^T) / denom, 64x64 tile GEMM over m ----------------
__global__ __launch_bounds__(256) void k7_gemmO() {
    int b  = blockIdx.z;
    int c0 = blockIdx.y * 64;
    int i0 = blockIdx.x * 64;
    int Mb = g_M[b];
    __shared__ float Vs[64][17];
    __shared__ float Ss[64][17];
    int tx = threadIdx.x & 15, ty = threadIdx.x >> 4;
    float acc[4][4] = {};
    int t = threadIdx.x;
    int row = t >> 2;           // 0..63
    int kq  = (t & 3) * 4;      // 0,4,8,12
    for (int m0 = 0; m0 < Mb; m0 += 16) {
        int mb = m0 + kq;
        const float* vsrc = g_Vg + ((size_t)b*C + c0 + row)*N + mb;
        const float* ssrc = g_S  + ((size_t)b*N + i0 + row)*N + mb;
        float4 v, s4;
        if (mb + 4 <= Mb) {
            v  = *(const float4*)vsrc;
            s4 = *(const float4*)ssrc;
        } else {
            v.x  = (mb+0 < Mb) ? vsrc[0] : 0.f;  v.y  = (mb+1 < Mb) ? vsrc[1] : 0.f;
            v.z  = (mb+2 < Mb) ? vsrc[2] : 0.f;  v.w  = (mb+3 < Mb) ? vsrc[3] : 0.f;
            s4.x = (mb+0 < Mb) ? ssrc[0] : 0.f;  s4.y = (mb+1 < Mb) ? ssrc[1] : 0.f;
            s4.z = (mb+2 < Mb) ? ssrc[2] : 0.f;  s4.w = (mb+3 < Mb) ? ssrc[3] : 0.f;
        }
        Vs[row][kq+0] = v.x;  Vs[row][kq+1] = v.y;  Vs[row][kq+2] = v.z;  Vs[row][kq+3] = v.w;
        Ss[row][kq+0] = s4.x; Ss[row][kq+1] = s4.y; Ss[row][kq+2] = s4.z; Ss[row][kq+3] = s4.w;
        __syncthreads();
        #pragma unroll
        for (int kk = 0; kk < 16; kk++) {
            float a0 = Vs[ty*4+0][kk], a1 = Vs[ty*4+1][kk], a2 = Vs[ty*4+2][kk], a3 = Vs[ty*4+3][kk];
            float b0 = Ss[tx*4+0][kk], b1 = Ss[tx*4+1][kk], b2 = Ss[tx*4+2][kk], b3 = Ss[tx*4+3][kk];
            acc[0][0] += a0*b0; acc[0][1] += a0*b1; acc[0][2] += a0*b2; acc[0][3] += a0*b3;
            acc[1][0] += a1*b0; acc[1][1] += a1*b1; acc[1][2] += a1*b2; acc[1][3] += a1*b3;
            acc[2][0] += a2*b0; acc[2][1] += a2*b1; acc[2][2] += a2*b2; acc[2][3] += a2*b3;
            acc[3][0] += a3*b0; acc[3][1] += a3*b1; acc[3][2] += a3*b2; acc[3][3] += a3*b3;
        }
        __syncthreads();
    }
    float dn[4];
    #pragma unroll
    for (int cI = 0; cI < 4; cI++) dn[cI] = 1.f / g_denom[b*N + i0 + tx*4 + cI];
    #pragma unroll
    for (int r = 0; r < 4; r++) {
        float* orow = g_ASBP + ((size_t)b*C + c0 + ty*4 + r)*N + i0;
        #pragma unroll
        for (int cI = 0; cI < 4; cI++) orow[tx*4 + cI] = acc[r][cI] * dn[cI];
    }
}

// ---------------- K8: final similarity ----------------
__global__ void k_out(const float* __restrict__ q, float* __restrict__ out) {
    int g = blockIdx.x * blockDim.x + threadIdx.x;
    int b = g / N, n = g % N;
    const float* qb  = q + (size_t)b*C*N + n;
    const float* fp1 = g_FP1 + b*C;
    const float* bgp = g_bgp + b*C;
    const float* asb = g_ASBP + (size_t)b*C*N + n;
    float df = 0.f, db = 0.f, bb = 0.f;
    for (int c = 0; c < C; c++) {
        float v  = qb[(size_t)c*N];
        float f1 = fp1[c];
        float bp = 0.3f * bgp[c] + 0.7f * asb[(size_t)c*N];
        df += v * f1;
        db += v * bp;
        bb += bp * bp;
    }
    float nq = g_qn[g];
    float nb = sqrtf(bb);
    out[(b*2 + 0)*N + n] = 10.f * db / fmaxf(nq * nb, 1e-8f);
    out[(b*2 + 1)*N + n] = 10.f * df / fmaxf(nq * g_nFP1[b], 1e-8f);
}

// ---------------- launch ----------------
extern "C" void kernel_launch(void* const* d_in, const int* in_sizes, int n_in,
                              void* d_out, int out_size) {
    const float* q    = (const float*)d_in[0];
    const float* sf   = (const float*)d_in[1];
    const int*   mask = (const int*)d_in[2];
    float* out = (float*)d_out;

    k_count  <<<B, 1024>>>(mask);
    k_pool   <<<B*C/8, 256>>>(sf, mask);
    k_norms  <<<B, 512>>>();
    k_pred   <<<B*N/256, 256>>>(q);
    k_weights<<<dim3(2, B), 1024>>>();
    k_gather <<<B*C, 128>>>(q);
    k_fgproto<<<B*C/8, 256>>>(q);
    k_fp1    <<<B, 512>>>();
    k5_gemmS <<<dim3(N/64, N/64, B), 256>>>(q);
    k_denom  <<<B*N/8, 256>>>();
    k7_gemmO <<<dim3(N/64, C/64, B), 256>>>();
    k_out    <<<B*N/256, 256>>>(q, out);
}

// round 5
// speedup vs baseline: 1.3205x; 1.3205x over previous
#include <cuda_runtime.h>
#include <math.h>

#define B 8
#define C 512
#define N 1024
#define TOPK 12
#define NCHUNK 8
#define PC (C/NCHUNK)   // 64 channels per chunk

// ---------------- device scratch (no allocations allowed) ----------------
__device__ float g_cntf[B], g_cntb[B];
__device__ float g_FP[B*C], g_BP[B*C];
__device__ float g_nFP[B], g_nBP[B];
__device__ float g_predfg[B*N], g_predbg[B*N];
__device__ float g_invn[B*N], g_qn[B*N];
__device__ float g_wf[B*N];
__device__ float g_wfsum[B];
__device__ int   g_idx[B*N];
__device__ int   g_M[B];
__device__ float g_invg[B*N];
__device__ float g_Vg[(size_t)B*C*N];        // gathered active columns of cur
__device__ float g_S[(size_t)B*N*N];         // exp scores (N x M per batch)
__device__ float g_denom[B*N];
__device__ float g_ASBP[(size_t)B*C*N];      // bg_local
__device__ float g_fgp[B*C], g_bgp[B*C];
__device__ float g_FP1[B*C];
__device__ float g_nFP1[B];

// split-C partials
__device__ float g_pdf[NCHUNK][B*N], g_pdb[NCHUNK][B*N], g_pqq[NCHUNK][B*N];
__device__ float g_odf[NCHUNK][B*N], g_odb[NCHUNK][B*N], g_obb[NCHUNK][B*N];

// ---------------- helpers ----------------
__device__ __forceinline__ float warp_sum(float v) {
    #pragma unroll
    for (int off = 16; off > 0; off >>= 1) v += __shfl_down_sync(0xffffffffu, v, off);
    return v;
}

// ---------------- K0: mask counts ----------------
__global__ void k_count(const int* __restrict__ mask) {
    int b = blockIdx.x, n = threadIdx.x;
    int mk = mask[b*N + n];
    int c1 = __syncthreads_count(mk == 1);
    int c0 = __syncthreads_count(mk == 0);
    if (n == 0) { g_cntf[b] = (float)c1; g_cntb[b] = (float)c0; }
}

// ---------------- K1: masked avg pool (FP/BP), one warp per (b,c) ----------------
__global__ void k_pool(const float* __restrict__ sf, const int* __restrict__ mask) {
    int w = blockIdx.x * 8 + (threadIdx.x >> 5);
    int lane = threadIdx.x & 31;
    int b = w / C, c = w % C;
    const float* row = sf + ((size_t)b*C + c)*N;
    const int* mrow = mask + b*N;
    float s1 = 0.f, s0 = 0.f;
    for (int n = lane; n < N; n += 32) {
        float v = row[n];
        if (mrow[n] == 1) s1 += v; else s0 += v;
    }
    s1 = warp_sum(s1); s0 = warp_sum(s0);
    if (lane == 0) {
        g_FP[b*C + c] = s1 / (g_cntf[b] + 1e-5f);
        g_BP[b*C + c] = s0 / (g_cntb[b] + 1e-5f);
    }
}

// ---------------- K1b: proto norms ----------------
__global__ void k_norms() {
    __shared__ float sh[512];
    int b = blockIdx.x, t = threadIdx.x;
    float f = g_FP[b*C + t];
    sh[t] = f*f; __syncthreads();
    for (int off = 256; off > 0; off >>= 1) { if (t < off) sh[t] += sh[t+off]; __syncthreads(); }
    if (t == 0) g_nFP[b] = sqrtf(sh[0]);
    __syncthreads();
    float p = g_BP[b*C + t];
    sh[t] = p*p; __syncthreads();
    for (int off = 256; off > 0; off >>= 1) { if (t < off) sh[t] += sh[t+off]; __syncthreads(); }
    if (t == 0) g_nBP[b] = sqrtf(sh[0]);
}

// ---------------- K2a: split-C partial dot products for pred ----------------
__global__ __launch_bounds__(256) void k_pred1(const float* __restrict__ q) {
    int g = blockIdx.x * blockDim.x + threadIdx.x;   // pixel id (b*N+n)
    int chunk = blockIdx.y;
    int b = g / N, n = g % N;
    const float* qb = q + (size_t)b*C*N + (size_t)chunk*PC*N + n;
    const float* fp = g_FP + b*C + chunk*PC;
    const float* bp = g_BP + b*C + chunk*PC;
    float df = 0.f, db = 0.f, qq = 0.f;
    #pragma unroll 16
    for (int c = 0; c < PC; c++) {
        float v = qb[(size_t)c*N];
        df += v * fp[c];
        db += v * bp[c];
        qq += v * v;
    }
    g_pdf[chunk][g] = df;
    g_pdb[chunk][g] = db;
    g_pqq[chunk][g] = qq;
}

// ---------------- K2b: combine + softmax epilogue ----------------
__global__ void k_pred2() {
    int g = blockIdx.x * blockDim.x + threadIdx.x;
    int b = g / N;
    float df = 0.f, db = 0.f, qq = 0.f;
    #pragma unroll
    for (int k = 0; k < NCHUNK; k++) {
        df += g_pdf[k][g];
        db += g_pdb[k][g];
        qq += g_pqq[k][g];
    }
    float nq = sqrtf(qq);
    float sf = 10.f * df / fmaxf(nq * g_nFP[b], 1e-8f);
    float sb = 10.f * db / fmaxf(nq * g_nBP[b], 1e-8f);
    float mx = fmaxf(sf, sb);
    float ef = expf(sf - mx), eb = expf(sb - mx);
    float inv = 1.f / (ef + eb);
    g_predfg[g] = ef * inv;
    g_predbg[g] = eb * inv;
    g_qn[g] = nq;
    g_invn[g] = 1.f / fmaxf(nq, 1e-20f);
}

// ---------------- K3: threshold / top-12 weight selection (+ bg compaction) ----------------
__global__ void k_weights() {
    int which = blockIdx.x;   // 0 = fg, 1 = bg
    int b = blockIdx.y;
    int tid = threadIdx.x;
    const float* pred = which ? (g_predbg + b*N) : (g_predfg + b*N);
    float thres = which ? 0.6f : 0.7f;
    float p = pred[tid];
    int flag = (p > thres) ? 1 : 0;
    int cnt = __syncthreads_count(flag);
    bool sel = false;
    if (cnt > 0) {
        sel = (flag != 0);
    } else {
        __shared__ float kv[1024];
        __shared__ int   ki[1024];
        bool taken = false;
        for (int t = 0; t < TOPK; t++) {
            kv[tid] = taken ? -1e30f : p;
            ki[tid] = tid;
            __syncthreads();
            for (int off = 512; off > 0; off >>= 1) {
                if (tid < off) {
                    float v2 = kv[tid+off]; int i2 = ki[tid+off];
                    if (v2 > kv[tid] || (v2 == kv[tid] && i2 < ki[tid])) { kv[tid] = v2; ki[tid] = i2; }
                }
                __syncthreads();
            }
            int win = ki[0];
            __syncthreads();
            if (tid == win) taken = true;
        }
        sel = taken;
    }
    float wsum = (cnt > 0) ? (float)cnt : (float)TOPK;
    if (which == 0) {
        g_wf[b*N + tid] = sel ? 1.f : 0.f;
        if (tid == 0) g_wfsum[b] = wsum;
    } else {
        __shared__ int ps[1024];
        int f = sel ? 1 : 0;
        ps[tid] = f; __syncthreads();
        for (int off = 1; off < 1024; off <<= 1) {
            int v = (tid >= off) ? ps[tid - off] : 0;
            __syncthreads();
            ps[tid] += v;
            __syncthreads();
        }
        if (f) {
            int pos = ps[tid] - 1;
            g_idx[b*N + pos]  = tid;
            g_invg[b*N + pos] = g_invn[b*N + tid];
        }
        if (tid == 1023) g_M[b] = ps[1023];
    }
}

// ---------------- K3b: gather active columns -> Vg, and bg_proto ----------------
__global__ void k_gather(const float* __restrict__ q) {
    int bc = blockIdx.x;
    int b = bc / C;
    int Mb = g_M[b];
    const int* idx = g_idx + b*N;
    const float* row = q + (size_t)bc*N;
    float* vrow = g_Vg + (size_t)bc*N;
    float s = 0.f;
    for (int m = threadIdx.x; m < Mb; m += blockDim.x) {
        float v = row[idx[m]];
        vrow[m] = v;
        s += v;
    }
    __shared__ float sh[128];
    int t = threadIdx.x;
    sh[t] = s; __syncthreads();
    for (int off = 64; off > 0; off >>= 1) { if (t < off) sh[t] += sh[t+off]; __syncthreads(); }
    if (t == 0) g_bgp[bc] = sh[0] / (float)Mb;
}

// ---------------- K4: fg proto, one warp per (b,c) ----------------
__global__ void k_fgproto(const float* __restrict__ q) {
    int w = blockIdx.x * 8 + (threadIdx.x >> 5);
    int lane = threadIdx.x & 31;
    int b = w / C;
    const float* row = q + (size_t)w*N;
    const float* wf = g_wf + b*N;
    float s = 0.f;
    for (int n = lane; n < N; n += 32) s += row[n] * wf[n];
    s = warp_sum(s);
    if (lane == 0) g_fgp[w] = s / g_wfsum[b];
}

// ---------------- K4b: FP1 and its norm ----------------
__global__ void k_fp1() {
    __shared__ float sh[512];
    int b = blockIdx.x, t = threadIdx.x;
    int i = b*C + t;
    float v = 0.5f * (g_FP[i] + g_fgp[i]);
    g_FP1[i] = v;
    sh[t] = v*v; __syncthreads();
    for (int off = 256; off > 0; off >>= 1) { if (t < off) sh[t] += sh[t+off]; __syncthreads(); }
    if (t == 0) g_nFP1[b] = sqrtf(sh[0]);
}

// ---------------- K5: S[i,m] = exp(2 * cn_i . cn_j(m)), 64x64 tile GEMM ----------------
__global__ __launch_bounds__(256) void k5_gemmS(const float* __restrict__ q) {
    int b  = blockIdx.z;
    int i0 = blockIdx.y * 64;
    int m0 = blockIdx.x * 64;
    int Mb = g_M[b];
    if (m0 >= Mb) return;
    __shared__ float As[16][64];
    __shared__ float Bs[16][64];
    int tx = threadIdx.x & 15, ty = threadIdx.x >> 4;
    float acc[4][4] = {};
    const float* qb = q + (size_t)b*C*N;
    const float* vg = g_Vg + (size_t)b*C*N;
    int t = threadIdx.x;
    int kk_l = t >> 4;            // 0..15
    int col_l = (t & 15) * 4;     // 0..60
    for (int k0 = 0; k0 < C; k0 += 16) {
        float4 va = *(const float4*)(qb + (size_t)(k0 + kk_l)*N + i0 + col_l);
        *(float4*)&As[kk_l][col_l] = va;
        float4 vb = *(const float4*)(vg + (size_t)(k0 + kk_l)*N + m0 + col_l);
        *(float4*)&Bs[kk_l][col_l] = vb;
        __syncthreads();
        #pragma unroll
        for (int kk = 0; kk < 16; kk++) {
            float4 fa = *(const float4*)&As[kk][ty*4];
            float4 fb = *(const float4*)&Bs[kk][tx*4];
            float a0 = fa.x, a1 = fa.y, a2 = fa.z, a3 = fa.w;
            float b0 = fb.x, b1 = fb.y, b2 = fb.z, b3 = fb.w;
            acc[0][0] += a0*b0; acc[0][1] += a0*b1; acc[0][2] += a0*b2; acc[0][3] += a0*b3;
            acc[1][0] += a1*b0; acc[1][1] += a1*b1; acc[1][2] += a1*b2; acc[1][3] += a1*b3;
            acc[2][0] += a2*b0; acc[2][1] += a2*b1; acc[2][2] += a2*b2; acc[2][3] += a2*b3;
            acc[3][0] += a3*b0; acc[3][1] += a3*b1; acc[3][2] += a3*b2; acc[3][3] += a3*b3;
        }
        __syncthreads();
    }
    float invi[4];
    #pragma unroll
    for (int r = 0; r < 4; r++) invi[r] = g_invn[b*N + i0 + ty*4 + r];
    #pragma unroll
    for (int cI = 0; cI < 4; cI++) {
        int m = m0 + tx*4 + cI;
        if (m < Mb) {
            float invj = g_invg[b*N + m];
            #pragma unroll
            for (int r = 0; r < 4; r++) {
                g_S[((size_t)b*N + i0 + ty*4 + r)*N + m] = __expf(2.f * acc[r][cI] * invi[r] * invj);
            }
        }
    }
}

// ---------------- K6: row sums (softmax denominator) ----------------
__global__ void k_denom() {
    int w = blockIdx.x * 8 + (threadIdx.x >> 5);
    int lane = threadIdx.x & 31;
    int b = w / N, i = w % N;
    int Mb = g_M[b];
    const float* srow = g_S + ((size_t)b*N + i)*N;
    float s = 0.f;
    for (int m = lane; m < Mb; m += 32) s += srow[m];
    s = warp_sum(s);
    if (lane == 0) g_denom[w] = s;
}

// ---------------- K7: ASBP = (Vg @ S^T) / denom, 64x64 tile GEMM over m ----------------
__global__ __launch_bounds__(256) void k7_gemmO() {
    int b  = blockIdx.z;
    int c0 = blockIdx.y * 64;
    int i0 = blockIdx.x * 64;
    int Mb = g_M[b];
    __shared__ float Vs[64][17];
    __shared__ float Ss[64][17];
    int tx = threadIdx.x & 15, ty = threadIdx.x >> 4;
    float acc[4][4] = {};
    int t = threadIdx.x;
    int row = t >> 2;           // 0..63
    int kq  = (t & 3) * 4;      // 0,4,8,12
    for (int m0 = 0; m0 < Mb; m0 += 16) {
        int mb = m0 + kq;
        const float* vsrc = g_Vg + ((size_t)b*C + c0 + row)*N + mb;
        const float* ssrc = g_S  + ((size_t)b*N + i0 + row)*N + mb;
        float4 v, s4;
        if (mb + 4 <= Mb) {
            v  = *(const float4*)vsrc;
            s4 = *(const float4*)ssrc;
        } else {
            v.x  = (mb+0 < Mb) ? vsrc[0] : 0.f;  v.y  = (mb+1 < Mb) ? vsrc[1] : 0.f;
            v.z  = (mb+2 < Mb) ? vsrc[2] : 0.f;  v.w  = (mb+3 < Mb) ? vsrc[3] : 0.f;
            s4.x = (mb+0 < Mb) ? ssrc[0] : 0.f;  s4.y = (mb+1 < Mb) ? ssrc[1] : 0.f;
            s4.z = (mb+2 < Mb) ? ssrc[2] : 0.f;  s4.w = (mb+3 < Mb) ? ssrc[3] : 0.f;
        }
        Vs[row][kq+0] = v.x;  Vs[row][kq+1] = v.y;  Vs[row][kq+2] = v.z;  Vs[row][kq+3] = v.w;
        Ss[row][kq+0] = s4.x; Ss[row][kq+1] = s4.y; Ss[row][kq+2] = s4.z; Ss[row][kq+3] = s4.w;
        __syncthreads();
        #pragma unroll
        for (int kk = 0; kk < 16; kk++) {
            float a0 = Vs[ty*4+0][kk], a1 = Vs[ty*4+1][kk], a2 = Vs[ty*4+2][kk], a3 = Vs[ty*4+3][kk];
            float b0 = Ss[tx*4+0][kk], b1 = Ss[tx*4+1][kk], b2 = Ss[tx*4+2][kk], b3 = Ss[tx*4+3][kk];
            acc[0][0] += a0*b0; acc[0][1] += a0*b1; acc[0][2] += a0*b2; acc[0][3] += a0*b3;
            acc[1][0] += a1*b0; acc[1][1] += a1*b1; acc[1][2] += a1*b2; acc[1][3] += a1*b3;
            acc[2][0] += a2*b0; acc[2][1] += a2*b1; acc[2][2] += a2*b2; acc[2][3] += a2*b3;
            acc[3][0] += a3*b0; acc[3][1] += a3*b1; acc[3][2] += a3*b2; acc[3][3] += a3*b3;
        }
        __syncthreads();
    }
    float dn[4];
    #pragma unroll
    for (int cI = 0; cI < 4; cI++) dn[cI] = 1.f / g_denom[b*N + i0 + tx*4 + cI];
    #pragma unroll
    for (int r = 0; r < 4; r++) {
        float* orow = g_ASBP + ((size_t)b*C + c0 + ty*4 + r)*N + i0;
        #pragma unroll
        for (int cI = 0; cI < 4; cI++) orow[tx*4 + cI] = acc[r][cI] * dn[cI];
    }
}

// ---------------- K8a: split-C partial sums for final similarity ----------------
__global__ __launch_bounds__(256) void k_out1(const float* __restrict__ q) {
    int g = blockIdx.x * blockDim.x + threadIdx.x;   // pixel id
    int chunk = blockIdx.y;
    int b = g / N, n = g % N;
    const float* qb  = q + (size_t)b*C*N + (size_t)chunk*PC*N + n;
    const float* fp1 = g_FP1 + b*C + chunk*PC;
    const float* bgp = g_bgp + b*C + chunk*PC;
    const float* asb = g_ASBP + (size_t)b*C*N + (size_t)chunk*PC*N + n;
    float df = 0.f, db = 0.f, bb = 0.f;
    #pragma unroll 16
    for (int c = 0; c < PC; c++) {
        float v  = qb[(size_t)c*N];
        float bp = 0.3f * bgp[c] + 0.7f * asb[(size_t)c*N];
        df += v * fp1[c];
        db += v * bp;
        bb += bp * bp;
    }
    g_odf[chunk][g] = df;
    g_odb[chunk][g] = db;
    g_obb[chunk][g] = bb;
}

// ---------------- K8b: combine + write output ----------------
__global__ void k_out2(float* __restrict__ out) {
    int g = blockIdx.x * blockDim.x + threadIdx.x;
    int b = g / N, n = g % N;
    float df = 0.f, db = 0.f, bb = 0.f;
    #pragma unroll
    for (int k = 0; k < NCHUNK; k++) {
        df += g_odf[k][g];
        db += g_odb[k][g];
        bb += g_obb[k][g];
    }
    float nq = g_qn[g];
    float nb = sqrtf(bb);
    out[(b*2 + 0)*N + n] = 10.f * db / fmaxf(nq * nb, 1e-8f);
    out[(b*2 + 1)*N + n] = 10.f * df / fmaxf(nq * g_nFP1[b], 1e-8f);
}

// ---------------- launch ----------------
extern "C" void kernel_launch(void* const* d_in, const int* in_sizes, int n_in,
                              void* d_out, int out_size) {
    const float* q    = (const float*)d_in[0];
    const float* sf   = (const float*)d_in[1];
    const int*   mask = (const int*)d_in[2];
    float* out = (float*)d_out;

    k_count  <<<B, 1024>>>(mask);
    k_pool   <<<B*C/8, 256>>>(sf, mask);
    k_norms  <<<B, 512>>>();
    k_pred1  <<<dim3(B*N/256, NCHUNK), 256>>>(q);
    k_pred2  <<<B*N/256, 256>>>();
    k_weights<<<dim3(2, B), 1024>>>();
    k_gather <<<B*C, 128>>>(q);
    k_fgproto<<<B*C/8, 256>>>(q);
    k_fp1    <<<B, 512>>>();
    k5_gemmS <<<dim3(N/64, N/64, B), 256>>>(q);
    k_denom  <<<B*N/8, 256>>>();
    k7_gemmO <<<dim3(N/64, C/64, B), 256>>>();
    k_out1   <<<dim3(B*N/256, NCHUNK), 256>>>(q);
    k_out2   <<<B*N/256, 256>>>(out);
}

// round 8
// speedup vs baseline: 2.1512x; 1.6291x over previous
#include <cuda_runtime.h>
#include <math.h>
#include <stdint.h>

#define B 8
#define C 512
#define N 1024
#define TOPK 12
#define NCHUNK 8
#define PC (C/NCHUNK)   // 64 channels per chunk

// ---------------- device scratch (no allocations allowed) ----------------
__device__ float g_cntf[B], g_cntb[B];
__device__ float g_FP[B*C], g_BP[B*C];
__device__ float g_nFP[B], g_nBP[B];
__device__ float g_predfg[B*N], g_predbg[B*N];
__device__ float g_invn[B*N], g_qn[B*N];
__device__ float g_wf[B*N];
__device__ float g_wfsum[B];
__device__ int   g_idx[B*N];
__device__ int   g_M[B];
__device__ int   g_Mpad[B];
__device__ float g_invg[B*N];
__device__ float g_Vg[(size_t)B*C*N];        // gathered active columns of cur (zero-padded to Mpad)
__device__ float g_S[(size_t)B*N*N];         // exp scores (N x Mpad per batch, zero beyond Mb)
__device__ float g_denom[B*N];
__device__ float g_ASBP[(size_t)B*C*N];      // bg_local
__device__ float g_fgp[B*C], g_bgp[B*C];
__device__ float g_FP1[B*C];
__device__ float g_nFP1[B];

// split-C partials
__device__ float g_pdf[NCHUNK][B*N], g_pdb[NCHUNK][B*N], g_pqq[NCHUNK][B*N];
__device__ float g_odf[NCHUNK][B*N], g_odb[NCHUNK][B*N], g_obb[NCHUNK][B*N];

// ---------------- helpers ----------------
__device__ __forceinline__ float warp_sum(float v) {
    #pragma unroll
    for (int off = 16; off > 0; off >>= 1) v += __shfl_down_sync(0xffffffffu, v, off);
    return v;
}

__device__ __forceinline__ uint32_t f2tf32(float f) {
    uint32_t u;
    asm("cvt.rna.tf32.f32 %0, %1;" : "=r"(u) : "f"(f));
    return u;
}

__device__ __forceinline__ void mma_tf32(float c[4],
                                         uint32_t a0, uint32_t a1, uint32_t a2, uint32_t a3,
                                         uint32_t b0, uint32_t b1) {
    asm volatile("mma.sync.aligned.m16n8k8.row.col.f32.tf32.tf32.f32 "
                 "{%0,%1,%2,%3}, {%4,%5,%6,%7}, {%8,%9}, {%0,%1,%2,%3};"
                 : "+f"(c[0]), "+f"(c[1]), "+f"(c[2]), "+f"(c[3])
                 : "r"(a0), "r"(a1), "r"(a2), "r"(a3), "r"(b0), "r"(b1));
}

// ---------------- K0: mask counts ----------------
__global__ void k_count(const int* __restrict__ mask) {
    int b = blockIdx.x, n = threadIdx.x;
    int mk = mask[b*N + n];
    int c1 = __syncthreads_count(mk == 1);
    int c0 = __syncthreads_count(mk == 0);
    if (n == 0) { g_cntf[b] = (float)c1; g_cntb[b] = (float)c0; }
}

// ---------------- K1: masked avg pool (FP/BP), one warp per (b,c) ----------------
__global__ void k_pool(const float* __restrict__ sf, const int* __restrict__ mask) {
    int w = blockIdx.x * 8 + (threadIdx.x >> 5);
    int lane = threadIdx.x & 31;
    int b = w / C, c = w % C;
    const float* row = sf + ((size_t)b*C + c)*N;
    const int* mrow = mask + b*N;
    float s1 = 0.f, s0 = 0.f;
    for (int n = lane; n < N; n += 32) {
        float v = row[n];
        if (mrow[n] == 1) s1 += v; else s0 += v;
    }
    s1 = warp_sum(s1); s0 = warp_sum(s0);
    if (lane == 0) {
        g_FP[b*C + c] = s1 / (g_cntf[b] + 1e-5f);
        g_BP[b*C + c] = s0 / (g_cntb[b] + 1e-5f);
    }
}

// ---------------- K1b: proto norms ----------------
__global__ void k_norms() {
    __shared__ float sh[512];
    int b = blockIdx.x, t = threadIdx.x;
    float f = g_FP[b*C + t];
    sh[t] = f*f; __syncthreads();
    for (int off = 256; off > 0; off >>= 1) { if (t < off) sh[t] += sh[t+off]; __syncthreads(); }
    if (t == 0) g_nFP[b] = sqrtf(sh[0]);
    __syncthreads();
    float p = g_BP[b*C + t];
    sh[t] = p*p; __syncthreads();
    for (int off = 256; off > 0; off >>= 1) { if (t < off) sh[t] += sh[t+off]; __syncthreads(); }
    if (t == 0) g_nBP[b] = sqrtf(sh[0]);
}

// ---------------- K2a: split-C partial dot products for pred ----------------
__global__ __launch_bounds__(256) void k_pred1(const float* __restrict__ q) {
    int g = blockIdx.x * blockDim.x + threadIdx.x;   // pixel id (b*N+n)
    int chunk = blockIdx.y;
    int b = g / N, n = g % N;
    const float* qb = q + (size_t)b*C*N + (size_t)chunk*PC*N + n;
    const float* fp = g_FP + b*C + chunk*PC;
    const float* bp = g_BP + b*C + chunk*PC;
    float df = 0.f, db = 0.f, qq = 0.f;
    #pragma unroll 16
    for (int c = 0; c < PC; c++) {
        float v = qb[(size_t)c*N];
        df += v * fp[c];
        db += v * bp[c];
        qq += v * v;
    }
    g_pdf[chunk][g] = df;
    g_pdb[chunk][g] = db;
    g_pqq[chunk][g] = qq;
}

// ---------------- K2b: combine + softmax epilogue ----------------
__global__ void k_pred2() {
    int g = blockIdx.x * blockDim.x + threadIdx.x;
    int b = g / N;
    float df = 0.f, db = 0.f, qq = 0.f;
    #pragma unroll
    for (int k = 0; k < NCHUNK; k++) {
        df += g_pdf[k][g];
        db += g_pdb[k][g];
        qq += g_pqq[k][g];
    }
    float nq = sqrtf(qq);
    float sf = 10.f * df / fmaxf(nq * g_nFP[b], 1e-8f);
    float sb = 10.f * db / fmaxf(nq * g_nBP[b], 1e-8f);
    float mx = fmaxf(sf, sb);
    float ef = expf(sf - mx), eb = expf(sb - mx);
    float inv = 1.f / (ef + eb);
    g_predfg[g] = ef * inv;
    g_predbg[g] = eb * inv;
    g_qn[g] = nq;
    g_invn[g] = 1.f / fmaxf(nq, 1e-20f);
}

// ---------------- K3: threshold / top-12 weight selection (+ bg compaction) ----------------
__global__ void k_weights() {
    int which = blockIdx.x;   // 0 = fg, 1 = bg
    int b = blockIdx.y;
    int tid = threadIdx.x;
    const float* pred = which ? (g_predbg + b*N) : (g_predfg + b*N);
    float thres = which ? 0.6f : 0.7f;
    float p = pred[tid];
    int flag = (p > thres) ? 1 : 0;
    int cnt = __syncthreads_count(flag);
    bool sel = false;
    if (cnt > 0) {
        sel = (flag != 0);
    } else {
        __shared__ float kv[1024];
        __shared__ int   ki[1024];
        bool taken = false;
        for (int t = 0; t < TOPK; t++) {
            kv[tid] = taken ? -1e30f : p;
            ki[tid] = tid;
            __syncthreads();
            for (int off = 512; off > 0; off >>= 1) {
                if (tid < off) {
                    float v2 = kv[tid+off]; int i2 = ki[tid+off];
                    if (v2 > kv[tid] || (v2 == kv[tid] && i2 < ki[tid])) { kv[tid] = v2; ki[tid] = i2; }
                }
                __syncthreads();
            }
            int win = ki[0];
            __syncthreads();
            if (tid == win) taken = true;
        }
        sel = taken;
    }
    float wsum = (cnt > 0) ? (float)cnt : (float)TOPK;
    if (which == 0) {
        g_wf[b*N + tid] = sel ? 1.f : 0.f;
        if (tid == 0) g_wfsum[b] = wsum;
    } else {
        __shared__ int ps[1024];
        int f = sel ? 1 : 0;
        ps[tid] = f; __syncthreads();
        for (int off = 1; off < 1024; off <<= 1) {
            int v = (tid >= off) ? ps[tid - off] : 0;
            __syncthreads();
            ps[tid] += v;
            __syncthreads();
        }
        if (f) {
            int pos = ps[tid] - 1;
            g_idx[b*N + pos]  = tid;
            g_invg[b*N + pos] = g_invn[b*N + tid];
        }
        if (tid == 1023) {
            g_M[b] = ps[1023];
            g_Mpad[b] = (ps[1023] + 63) & ~63;
        }
    }
}

// ---------------- K3b: gather active columns -> Vg (zero-padded), and bg_proto ----------------
__global__ void k_gather(const float* __restrict__ q) {
    int bc = blockIdx.x;
    int b = bc / C;
    int Mb = g_M[b];
    int Mpad = g_Mpad[b];
    const int* idx = g_idx + b*N;
    const float* row = q + (size_t)bc*N;
    float* vrow = g_Vg + (size_t)bc*N;
    float s = 0.f;
    for (int m = threadIdx.x; m < Mb; m += blockDim.x) {
        float v = row[idx[m]];
        vrow[m] = v;
        s += v;
    }
    for (int m = Mb + threadIdx.x; m < Mpad; m += blockDim.x) vrow[m] = 0.f;
    __shared__ float sh[128];
    int t = threadIdx.x;
    sh[t] = s; __syncthreads();
    for (int off = 64; off > 0; off >>= 1) { if (t < off) sh[t] += sh[t+off]; __syncthreads(); }
    if (t == 0) g_bgp[bc] = sh[0] / (float)Mb;
}

// ---------------- K4: fg proto, one warp per (b,c) ----------------
__global__ void k_fgproto(const float* __restrict__ q) {
    int w = blockIdx.x * 8 + (threadIdx.x >> 5);
    int lane = threadIdx.x & 31;
    int b = w / C;
    const float* row = q + (size_t)w*N;
    const float* wf = g_wf + b*N;
    float s = 0.f;
    for (int n = lane; n < N; n += 32) s += row[n] * wf[n];
    s = warp_sum(s);
    if (lane == 0) g_fgp[w] = s / g_wfsum[b];
}

// ---------------- K4b: FP1 and its norm ----------------
__global__ void k_fp1() {
    __shared__ float sh[512];
    int b = blockIdx.x, t = threadIdx.x;
    int i = b*C + t;
    float v = 0.5f * (g_FP[i] + g_fgp[i]);
    g_FP1[i] = v;
    sh[t] = v*v; __syncthreads();
    for (int off = 256; off > 0; off >>= 1) { if (t < off) sh[t] += sh[t+off]; __syncthreads(); }
    if (t == 0) g_nFP1[b] = sqrtf(sh[0]);
}

// ---------------- K5: S = exp(2 * cn^T cn) via tf32 mma, 64x64 block tiles ----------------
// A tile: q[k][i] (K=channel, 64 i cols), B tile: Vg[k][m].
// smem layout [k][col] with row stride 72 floats -> frag LDS bank = lane + const (conflict-free).
__global__ __launch_bounds__(256) void k5_mma(const float* __restrict__ q) {
    int b  = blockIdx.z;
    int i0 = blockIdx.y * 64;
    int m0 = blockIdx.x * 64;
    int Mb = g_M[b];
    int Mpad = g_Mpad[b];
    if (m0 >= Mpad) return;

    __shared__ uint32_t As[32][72];
    __shared__ uint32_t Bs[32][72];

    int t = threadIdx.x;
    int lane = t & 31, w = t >> 5;
    int gid = lane >> 2, tig = lane & 3;
    int iw = (w >> 1) * 16;       // warp i base within tile
    int mw = (w & 1) * 32;        // warp m base within tile

    float acc[4][4] = {};         // [n-tile][c-reg]

    const float* qb = q + (size_t)b*C*N;
    const float* vg = g_Vg + (size_t)b*C*N;

    int lr = t >> 4;              // 0..15  (k row within half-chunk)
    int lc = (t & 15) * 4;        // 0..60  (col)

    for (int k0 = 0; k0 < C; k0 += 32) {
        #pragma unroll
        for (int rr = 0; rr < 2; rr++) {
            int k = lr + rr * 16;
            float4 va = *(const float4*)(qb + (size_t)(k0 + k)*N + i0 + lc);
            As[k][lc+0] = f2tf32(va.x); As[k][lc+1] = f2tf32(va.y);
            As[k][lc+2] = f2tf32(va.z); As[k][lc+3] = f2tf32(va.w);
            float4 vb = *(const float4*)(vg + (size_t)(k0 + k)*N + m0 + lc);
            Bs[k][lc+0] = f2tf32(vb.x); Bs[k][lc+1] = f2tf32(vb.y);
            Bs[k][lc+2] = f2tf32(vb.z); Bs[k][lc+3] = f2tf32(vb.w);
        }
        __syncthreads();
        #pragma unroll
        for (int kk = 0; kk < 32; kk += 8) {
            uint32_t a0 = As[kk + tig    ][iw + gid];
            uint32_t a1 = As[kk + tig    ][iw + gid + 8];
            uint32_t a2 = As[kk + 4 + tig][iw + gid];
            uint32_t a3 = As[kk + 4 + tig][iw + gid + 8];
            #pragma unroll
            for (int j = 0; j < 4; j++) {
                uint32_t b0 = Bs[kk + tig    ][mw + 8*j + gid];
                uint32_t b1 = Bs[kk + 4 + tig][mw + 8*j + gid];
                mma_tf32(acc[j], a0, a1, a2, a3, b0, b1);
            }
        }
        __syncthreads();
    }

    int ilo = i0 + iw + gid;
    int ihi = ilo + 8;
    float invlo = g_invn[b*N + ilo];
    float invhi = g_invn[b*N + ihi];
    #pragma unroll
    for (int j = 0; j < 4; j++) {
        int m = m0 + mw + 8*j + 2*tig;
        bool in0 = m < Mb, in1 = (m + 1) < Mb;
        float ig0 = in0 ? g_invg[b*N + m]     : 0.f;
        float ig1 = in1 ? g_invg[b*N + m + 1] : 0.f;
        float* r0 = g_S + ((size_t)b*N + ilo)*N + m;
        float* r1 = g_S + ((size_t)b*N + ihi)*N + m;
        r0[0] = in0 ? __expf(2.f * acc[j][0] * invlo * ig0) : 0.f;
        r0[1] = in1 ? __expf(2.f * acc[j][1] * invlo * ig1) : 0.f;
        r1[0] = in0 ? __expf(2.f * acc[j][2] * invhi * ig0) : 0.f;
        r1[1] = in1 ? __expf(2.f * acc[j][3] * invhi * ig1) : 0.f;
    }
}

// ---------------- K6: row sums (softmax denominator) ----------------
__global__ void k_denom() {
    int w = blockIdx.x * 8 + (threadIdx.x >> 5);
    int lane = threadIdx.x & 31;
    int b = w / N, i = w % N;
    int Mb = g_M[b];
    const float* srow = g_S + ((size_t)b*N + i)*N;
    float s = 0.f;
    for (int m = lane; m < Mb; m += 32) s += srow[m];
    s = warp_sum(s);
    if (lane == 0) g_denom[w] = s;
}

// ---------------- K7: ASBP = (Vg @ S^T) / denom via tf32 mma, 64x64 block tiles ----------------
// A tile: Vg[c][m] (K = m), B tile: S[i][m]. smem [row][m] stride 36 -> frag bank = lane + const.
__global__ __launch_bounds__(256) void k7_mma() {
    int b  = blockIdx.z;
    int c0 = blockIdx.y * 64;
    int i0 = blockIdx.x * 64;
    int Mpad = g_Mpad[b];

    __shared__ uint32_t As[64][36];
    __shared__ uint32_t Bs[64][36];

    int t = threadIdx.x;
    int lane = t & 31, w = t >> 5;
    int gid = lane >> 2, tig = lane & 3;
    int cw = (w >> 1) * 16;
    int iw = (w & 1) * 32;

    float acc[4][4] = {};

    int lr = t >> 3;              // 0..31 (row within half)
    int lc = (t & 7) * 4;         // 0..28 (m col)

    for (int m0 = 0; m0 < Mpad; m0 += 32) {
        #pragma unroll
        for (int rr = 0; rr < 2; rr++) {
            int r = lr + rr * 32;
            float4 va = *(const float4*)(g_Vg + ((size_t)b*C + c0 + r)*N + m0 + lc);
            As[r][lc+0] = f2tf32(va.x); As[r][lc+1] = f2tf32(va.y);
            As[r][lc+2] = f2tf32(va.z); As[r][lc+3] = f2tf32(va.w);
            float4 vb = *(const float4*)(g_S + ((size_t)b*N + i0 + r)*N + m0 + lc);
            Bs[r][lc+0] = f2tf32(vb.x); Bs[r][lc+1] = f2tf32(vb.y);
            Bs[r][lc+2] = f2tf32(vb.z); Bs[r][lc+3] = f2tf32(vb.w);
        }
        __syncthreads();
        #pragma unroll
        for (int kk = 0; kk < 32; kk += 8) {
            uint32_t a0 = As[cw + gid    ][kk + tig];
            uint32_t a1 = As[cw + gid + 8][kk + tig];
            uint32_t a2 = As[cw + gid    ][kk + 4 + tig];
            uint32_t a3 = As[cw + gid + 8][kk + 4 + tig];
            #pragma unroll
            for (int j = 0; j < 4; j++) {
                uint32_t b0 = Bs[iw + 8*j + gid][kk + tig];
                uint32_t b1 = Bs[iw + 8*j + gid][kk + 4 + tig];
                mma_tf32(acc[j], a0, a1, a2, a3, b0, b1);
            }
        }
        __syncthreads();
    }

    int clo = c0 + cw + gid;
    int chi = clo + 8;
    #pragma unroll
    for (int j = 0; j < 4; j++) {
        int i = i0 + iw + 8*j + 2*tig;
        float d0 = 1.f / g_denom[b*N + i];
        float d1 = 1.f / g_denom[b*N + i + 1];
        float* r0 = g_ASBP + ((size_t)b*C + clo)*N + i;
        float* r1 = g_ASBP + ((size_t)b*C + chi)*N + i;
        r0[0] = acc[j][0] * d0;
        r0[1] = acc[j][1] * d1;
        r1[0] = acc[j][2] * d0;
        r1[1] = acc[j][3] * d1;
    }
}

// ---------------- K8a: split-C partial sums for final similarity ----------------
__global__ __launch_bounds__(256) void k_out1(const float* __restrict__ q) {
    int g = blockIdx.x * blockDim.x + threadIdx.x;   // pixel id
    int chunk = blockIdx.y;
    int b = g / N, n = g % N;
    const float* qb  = q + (size_t)b*C*N + (size_t)chunk*PC*N + n;
    const float* fp1 = g_FP1 + b*C + chunk*PC;
    const float* bgp = g_bgp + b*C + chunk*PC;
    const float* asb = g_ASBP + (size_t)b*C*N + (size_t)chunk*PC*N + n;
    float df = 0.f, db = 0.f, bb = 0.f;
    #pragma unroll 16
    for (int c = 0; c < PC; c++) {
        float v  = qb[(size_t)c*N];
        float bp = 0.3f * bgp[c] + 0.7f * asb[(size_t)c*N];
        df += v * fp1[c];
        db += v * bp;
        bb += bp * bp;
    }
    g_odf[chunk][g] = df;
    g_odb[chunk][g] = db;
    g_obb[chunk][g] = bb;
}

// ---------------- K8b: combine + write output ----------------
__global__ void k_out2(float* __restrict__ out) {
    int g = blockIdx.x * blockDim.x + threadIdx.x;
    int b = g / N, n = g % N;
    float df = 0.f, db = 0.f, bb = 0.f;
    #pragma unroll
    for (int k = 0; k < NCHUNK; k++) {
        df += g_odf[k][g];
        db += g_odb[k][g];
        bb += g_obb[k][g];
    }
    float nq = g_qn[g];
    float nb = sqrtf(bb);
    out[(b*2 + 0)*N + n] = 10.f * db / fmaxf(nq * nb, 1e-8f);
    out[(b*2 + 1)*N + n] = 10.f * df / fmaxf(nq * g_nFP1[b], 1e-8f);
}

// ---------------- launch ----------------
extern "C" void kernel_launch(void* const* d_in, const int* in_sizes, int n_in,
                              void* d_out, int out_size) {
    const float* q    = (const float*)d_in[0];
    const float* sf   = (const float*)d_in[1];
    const int*   mask = (const int*)d_in[2];
    float* out = (float*)d_out;

    k_count  <<<B, 1024>>>(mask);
    k_pool   <<<B*C/8, 256>>>(sf, mask);
    k_norms  <<<B, 512>>>();
    k_pred1  <<<dim3(B*N/256, NCHUNK), 256>>>(q);
    k_pred2  <<<B*N/256, 256>>>();
    k_weights<<<dim3(2, B), 1024>>>();
    k_gather <<<B*C, 128>>>(q);
    k_fgproto<<<B*C/8, 256>>>(q);
    k_fp1    <<<B, 512>>>();
    k5_mma   <<<dim3(N/64, N/64, B), 256>>>(q);
    k_denom  <<<B*N/8, 256>>>();
    k7_mma   <<<dim3(N/64, C/64, B), 256>>>();
    k_out1   <<<dim3(B*N/256, NCHUNK), 256>>>(q);
    k_out2   <<<B*N/256, 256>>>(out);
}

// round 9
// speedup vs baseline: 2.6640x; 1.2384x over previous
#include <cuda_runtime.h>
#include <math.h>
#include <stdint.h>

#define B 8
#define C 512
#define N 1024
#define TOPK 12
#define NCHP 16
#define PC (C/NCHP)     // 32 channels per pred chunk
#define OC 8            // output c-blocks (C/64)

// ---------------- device scratch (no allocations allowed) ----------------
__device__ float g_cntf[B], g_cntb[B];
__device__ float g_FP[B*C], g_BP[B*C];
__device__ float g_nFP[B], g_nBP[B];
__device__ float g_predfg[B*N], g_predbg[B*N];
__device__ float g_invn[B*N], g_qn[B*N];
__device__ float g_wf[B*N];
__device__ float g_wfsum[B];
__device__ int   g_idx[B*N];
__device__ int   g_M[B];
__device__ int   g_Mpad[B];
__device__ float g_invg[B*N];
__device__ float g_Vg[(size_t)B*C*N];        // gathered active columns (zero-padded to Mpad)
__device__ float g_S[(size_t)B*N*N];         // exp scores (N x Mpad per batch, zero beyond Mb)
__device__ float g_denom[B*N];
__device__ float g_fgp[B*C], g_bgp[B*C];
__device__ float g_FP1[B*C];
__device__ float g_nFP1[B];

// split partials
__device__ float g_pdf[NCHP][B*N], g_pdb[NCHP][B*N], g_pqq[NCHP][B*N];
__device__ float g_odf[OC][B*N], g_odb[OC][B*N], g_obb[OC][B*N];

// ---------------- helpers ----------------
__device__ __forceinline__ float warp_sum(float v) {
    #pragma unroll
    for (int off = 16; off > 0; off >>= 1) v += __shfl_down_sync(0xffffffffu, v, off);
    return v;
}

__device__ __forceinline__ uint32_t f2tf32(float f) {
    uint32_t u;
    asm("cvt.rna.tf32.f32 %0, %1;" : "=r"(u) : "f"(f));
    return u;
}

__device__ __forceinline__ void mma_tf32(float c[4],
                                         uint32_t a0, uint32_t a1, uint32_t a2, uint32_t a3,
                                         uint32_t b0, uint32_t b1) {
    asm volatile("mma.sync.aligned.m16n8k8.row.col.f32.tf32.tf32.f32 "
                 "{%0,%1,%2,%3}, {%4,%5,%6,%7}, {%8,%9}, {%0,%1,%2,%3};"
                 : "+f"(c[0]), "+f"(c[1]), "+f"(c[2]), "+f"(c[3])
                 : "r"(a0), "r"(a1), "r"(a2), "r"(a3), "r"(b0), "r"(b1));
}

// ---------------- K0: mask counts ----------------
__global__ void k_count(const int* __restrict__ mask) {
    int b = blockIdx.x, n = threadIdx.x;
    int mk = mask[b*N + n];
    int c1 = __syncthreads_count(mk == 1);
    int c0 = __syncthreads_count(mk == 0);
    if (n == 0) { g_cntf[b] = (float)c1; g_cntb[b] = (float)c0; }
}

// ---------------- K1: masked avg pool (FP/BP), one warp per (b,c), float4 ----------------
__global__ void k_pool(const float* __restrict__ sf, const int* __restrict__ mask) {
    int w = blockIdx.x * 8 + (threadIdx.x >> 5);
    int lane = threadIdx.x & 31;
    int b = w / C, c = w % C;
    const float4* row4 = (const float4*)(sf + (size_t)w*N);
    const int4*   m4   = (const int4*)(mask + b*N);
    float s1 = 0.f, s0 = 0.f;
    #pragma unroll
    for (int i = 0; i < 8; i++) {
        int p = lane + i*32;
        float4 v = row4[p];
        int4 mk = m4[p];
        float fx = (float)mk.x, fy = (float)mk.y, fz = (float)mk.z, fw = (float)mk.w;
        s1 += fx*v.x + fy*v.y + fz*v.z + fw*v.w;
        s0 += (1.f-fx)*v.x + (1.f-fy)*v.y + (1.f-fz)*v.z + (1.f-fw)*v.w;
    }
    s1 = warp_sum(s1); s0 = warp_sum(s0);
    if (lane == 0) {
        g_FP[b*C + c] = s1 / (g_cntf[b] + 1e-5f);
        g_BP[b*C + c] = s0 / (g_cntb[b] + 1e-5f);
    }
}

// ---------------- K1b: proto norms ----------------
__global__ void k_norms() {
    __shared__ float sh[512];
    int b = blockIdx.x, t = threadIdx.x;
    float f = g_FP[b*C + t];
    sh[t] = f*f; __syncthreads();
    for (int off = 256; off > 0; off >>= 1) { if (t < off) sh[t] += sh[t+off]; __syncthreads(); }
    if (t == 0) g_nFP[b] = sqrtf(sh[0]);
    __syncthreads();
    float p = g_BP[b*C + t];
    sh[t] = p*p; __syncthreads();
    for (int off = 256; off > 0; off >>= 1) { if (t < off) sh[t] += sh[t+off]; __syncthreads(); }
    if (t == 0) g_nBP[b] = sqrtf(sh[0]);
}

// ---------------- K2a: split-C partial dot products for pred ----------------
__global__ __launch_bounds__(256) void k_pred1(const float* __restrict__ q) {
    int g = blockIdx.x * blockDim.x + threadIdx.x;   // pixel id (b*N+n)
    int chunk = blockIdx.y;
    int b = g / N, n = g % N;
    const float* qb = q + (size_t)b*C*N + (size_t)chunk*PC*N + n;
    const float* fp = g_FP + b*C + chunk*PC;
    const float* bp = g_BP + b*C + chunk*PC;
    float df = 0.f, db = 0.f, qq = 0.f;
    #pragma unroll 16
    for (int c = 0; c < PC; c++) {
        float v = qb[(size_t)c*N];
        df += v * fp[c];
        db += v * bp[c];
        qq += v * v;
    }
    g_pdf[chunk][g] = df;
    g_pdb[chunk][g] = db;
    g_pqq[chunk][g] = qq;
}

// ---------------- K2b: combine + softmax epilogue (+ zero denom) ----------------
__global__ void k_pred2() {
    int g = blockIdx.x * blockDim.x + threadIdx.x;
    int b = g / N;
    float df = 0.f, db = 0.f, qq = 0.f;
    #pragma unroll
    for (int k = 0; k < NCHP; k++) {
        df += g_pdf[k][g];
        db += g_pdb[k][g];
        qq += g_pqq[k][g];
    }
    float nq = sqrtf(qq);
    float sf = 10.f * df / fmaxf(nq * g_nFP[b], 1e-8f);
    float sb = 10.f * db / fmaxf(nq * g_nBP[b], 1e-8f);
    float mx = fmaxf(sf, sb);
    float ef = expf(sf - mx), eb = expf(sb - mx);
    float inv = 1.f / (ef + eb);
    g_predfg[g] = ef * inv;
    g_predbg[g] = eb * inv;
    g_qn[g] = nq;
    g_invn[g] = 1.f / fmaxf(nq, 1e-20f);
    g_denom[g] = 0.f;          // cleared for k5's atomic row sums
}

// ---------------- K3: threshold / top-12 selection (shfl argmax + ballot scan) ----------------
__global__ void k_weights() {
    int which = blockIdx.x;   // 0 = fg, 1 = bg
    int b = blockIdx.y;
    int tid = threadIdx.x;
    int lane = tid & 31, w = tid >> 5;
    const float* pred = which ? (g_predbg + b*N) : (g_predfg + b*N);
    float thres = which ? 0.6f : 0.7f;
    float p = pred[tid];
    int flag = (p > thres) ? 1 : 0;
    int cnt = __syncthreads_count(flag);

    __shared__ float shv[32];
    __shared__ int   shi[32];
    __shared__ int   swin;

    bool sel;
    if (cnt > 0) {
        sel = (flag != 0);
    } else {
        bool taken = false;
        for (int it = 0; it < TOPK; it++) {
            float v = taken ? -1e30f : p;
            int id = tid;
            #pragma unroll
            for (int off = 16; off > 0; off >>= 1) {
                float ov = __shfl_down_sync(0xffffffffu, v, off);
                int   oi = __shfl_down_sync(0xffffffffu, id, off);
                if (ov > v || (ov == v && oi < id)) { v = ov; id = oi; }
            }
            if (lane == 0) { shv[w] = v; shi[w] = id; }
            __syncthreads();
            if (w == 0) {
                float v2 = shv[lane]; int i2 = shi[lane];
                #pragma unroll
                for (int off = 16; off > 0; off >>= 1) {
                    float ov = __shfl_down_sync(0xffffffffu, v2, off);
                    int   oi = __shfl_down_sync(0xffffffffu, i2, off);
                    if (ov > v2 || (ov == v2 && oi < i2)) { v2 = ov; i2 = oi; }
                }
                if (lane == 0) swin = i2;
            }
            __syncthreads();
            if (tid == swin) taken = true;
        }
        sel = taken;
    }

    float wsum = (cnt > 0) ? (float)cnt : (float)TOPK;
    if (which == 0) {
        g_wf[b*N + tid] = sel ? 1.f : 0.f;
        if (tid == 0) g_wfsum[b] = wsum;
    } else {
        __shared__ int wtot[32];
        __shared__ int wbase[33];
        unsigned bal = __ballot_sync(0xffffffffu, sel);
        int wincl = __popc(bal & (0xffffffffu >> (31 - lane)));   // inclusive within warp
        if (lane == 31) wtot[w] = wincl;                          // warp total
        __syncthreads();
        if (w == 0) {
            int tv = wtot[lane];
            int x = tv;
            #pragma unroll
            for (int off = 1; off < 32; off <<= 1) {
                int y = __shfl_up_sync(0xffffffffu, x, off);
                if (lane >= off) x += y;
            }
            wbase[lane] = x - tv;                                  // exclusive base
            if (lane == 31) wbase[32] = x;                         // total
        }
        __syncthreads();
        if (sel) {
            int pos = wbase[w] + wincl - 1;
            g_idx[b*N + pos]  = tid;
            g_invg[b*N + pos] = g_invn[b*N + tid];
        }
        if (tid == 0) {
            int M = wbase[32];
            g_M[b] = M;
            g_Mpad[b] = (M + 63) & ~63;
        }
    }
}

// ---------------- K3b: fused fg-proto + gather + bg-proto (one block per (b,c)) ----------------
__global__ void k_gfg(const float* __restrict__ q) {
    int bc = blockIdx.x;
    int b = bc / C;
    int t = threadIdx.x, lane = t & 31, w = t >> 5;
    __shared__ float sh[4];

    const float4* row4 = (const float4*)(q + (size_t)bc*N);
    const float4* wf4  = (const float4*)(g_wf + b*N);
    float s = 0.f;
    #pragma unroll
    for (int i = 0; i < 2; i++) {
        int p = t + i*128;
        float4 v = row4[p], wv = wf4[p];
        s += v.x*wv.x + v.y*wv.y + v.z*wv.z + v.w*wv.w;
    }
    s = warp_sum(s);
    if (lane == 0) sh[w] = s;
    __syncthreads();
    if (t == 0) g_fgp[bc] = (sh[0]+sh[1]+sh[2]+sh[3]) / g_wfsum[b];

    int Mb = g_M[b], Mpad = g_Mpad[b];
    const int* idx = g_idx + b*N;
    const float* row = q + (size_t)bc*N;
    float* vrow = g_Vg + (size_t)bc*N;
    float sb = 0.f;
    for (int m = t; m < Mb; m += 128) {       // row is L1-hot from the pass above
        float v = row[idx[m]];
        vrow[m] = v;
        sb += v;
    }
    for (int m = Mb + t; m < Mpad; m += 128) vrow[m] = 0.f;
    sb = warp_sum(sb);
    __syncthreads();
    if (lane == 0) sh[w] = sb;
    __syncthreads();
    if (t == 0) g_bgp[bc] = (sh[0]+sh[1]+sh[2]+sh[3]) / (float)Mb;
}

// ---------------- K4b: FP1 and its norm ----------------
__global__ void k_fp1() {
    __shared__ float sh[512];
    int b = blockIdx.x, t = threadIdx.x;
    int i = b*C + t;
    float v = 0.5f * (g_FP[i] + g_fgp[i]);
    g_FP1[i] = v;
    sh[t] = v*v; __syncthreads();
    for (int off = 256; off > 0; off >>= 1) { if (t < off) sh[t] += sh[t+off]; __syncthreads(); }
    if (t == 0) g_nFP1[b] = sqrtf(sh[0]);
}

// ---------------- K5: S = exp(2 cn^T cn) via tf32 mma + fused denom atomics ----------------
__global__ __launch_bounds__(256) void k5_mma(const float* __restrict__ q) {
    int b  = blockIdx.z;
    int i0 = blockIdx.y * 64;
    int m0 = blockIdx.x * 64;
    int Mb = g_M[b];
    int Mpad = g_Mpad[b];
    if (m0 >= Mpad) return;

    __shared__ uint32_t As[32][72];
    __shared__ uint32_t Bs[32][72];

    int t = threadIdx.x;
    int lane = t & 31, w = t >> 5;
    int gid = lane >> 2, tig = lane & 3;
    int iw = (w >> 1) * 16;
    int mw = (w & 1) * 32;

    float acc[4][4] = {};

    const float* qb = q + (size_t)b*C*N;
    const float* vg = g_Vg + (size_t)b*C*N;

    int lr = t >> 4;
    int lc = (t & 15) * 4;

    for (int k0 = 0; k0 < C; k0 += 32) {
        #pragma unroll
        for (int rr = 0; rr < 2; rr++) {
            int k = lr + rr * 16;
            float4 va = *(const float4*)(qb + (size_t)(k0 + k)*N + i0 + lc);
            As[k][lc+0] = f2tf32(va.x); As[k][lc+1] = f2tf32(va.y);
            As[k][lc+2] = f2tf32(va.z); As[k][lc+3] = f2tf32(va.w);
            float4 vb = *(const float4*)(vg + (size_t)(k0 + k)*N + m0 + lc);
            Bs[k][lc+0] = f2tf32(vb.x); Bs[k][lc+1] = f2tf32(vb.y);
            Bs[k][lc+2] = f2tf32(vb.z); Bs[k][lc+3] = f2tf32(vb.w);
        }
        __syncthreads();
        #pragma unroll
        for (int kk = 0; kk < 32; kk += 8) {
            uint32_t a0 = As[kk + tig    ][iw + gid];
            uint32_t a1 = As[kk + tig    ][iw + gid + 8];
            uint32_t a2 = As[kk + 4 + tig][iw + gid];
            uint32_t a3 = As[kk + 4 + tig][iw + gid + 8];
            #pragma unroll
            for (int j = 0; j < 4; j++) {
                uint32_t b0 = Bs[kk + tig    ][mw + 8*j + gid];
                uint32_t b1 = Bs[kk + 4 + tig][mw + 8*j + gid];
                mma_tf32(acc[j], a0, a1, a2, a3, b0, b1);
            }
        }
        __syncthreads();
    }

    int ilo = i0 + iw + gid;
    int ihi = ilo + 8;
    float invlo = g_invn[b*N + ilo];
    float invhi = g_invn[b*N + ihi];
    float slo = 0.f, shi2 = 0.f;
    #pragma unroll
    for (int j = 0; j < 4; j++) {
        int m = m0 + mw + 8*j + 2*tig;
        bool in0 = m < Mb, in1 = (m + 1) < Mb;
        float ig0 = in0 ? g_invg[b*N + m]     : 0.f;
        float ig1 = in1 ? g_invg[b*N + m + 1] : 0.f;
        float e00 = in0 ? __expf(2.f * acc[j][0] * invlo * ig0) : 0.f;
        float e01 = in1 ? __expf(2.f * acc[j][1] * invlo * ig1) : 0.f;
        float e10 = in0 ? __expf(2.f * acc[j][2] * invhi * ig0) : 0.f;
        float e11 = in1 ? __expf(2.f * acc[j][3] * invhi * ig1) : 0.f;
        float* r0 = g_S + ((size_t)b*N + ilo)*N + m;
        float* r1 = g_S + ((size_t)b*N + ihi)*N + m;
        r0[0] = e00; r0[1] = e01;
        r1[0] = e10; r1[1] = e11;
        slo  += e00 + e01;
        shi2 += e10 + e11;
    }
    // reduce over the 4 tig lanes (lanes gid*4 + tig)
    slo  += __shfl_xor_sync(0xffffffffu, slo, 1);
    slo  += __shfl_xor_sync(0xffffffffu, slo, 2);
    shi2 += __shfl_xor_sync(0xffffffffu, shi2, 1);
    shi2 += __shfl_xor_sync(0xffffffffu, shi2, 2);
    if (tig == 0) {
        atomicAdd(&g_denom[b*N + ilo], slo);
        atomicAdd(&g_denom[b*N + ihi], shi2);
    }
}

// ---------------- K7: bg_local GEMM + fused final-similarity partials ----------------
// A tile: Vg[c][m], B tile: S[i][m]; epilogue computes bp = 0.3 bgp + 0.7 acc/denom
// into smem and emits per-(c-block, pixel) partial sums of df/db/bb.
__global__ __launch_bounds__(256) void k7_mma(const float* __restrict__ q) {
    int b  = blockIdx.z;
    int c0 = blockIdx.y * 64;
    int i0 = blockIdx.x * 64;
    int Mpad = g_Mpad[b];

    __shared__ float sraw[4608];   // aliased: As/Bs (2*64*36 u32) then bp tile (64*65 f32)
    #define K7_AS(r,c) (((uint32_t*)sraw)[(r)*36+(c)])
    #define K7_BS(r,c) (((uint32_t*)sraw)[2304+(r)*36+(c)])
    #define K7_BP(r,c) (sraw[(r)*65+(c)])

    int t = threadIdx.x;
    int lane = t & 31, w = t >> 5;
    int gid = lane >> 2, tig = lane & 3;
    int cw = (w >> 1) * 16;
    int iw = (w & 1) * 32;

    float acc[4][4] = {};

    int lr = t >> 3;
    int lc = (t & 7) * 4;

    for (int m0 = 0; m0 < Mpad; m0 += 32) {
        #pragma unroll
        for (int rr = 0; rr < 2; rr++) {
            int r = lr + rr * 32;
            float4 va = *(const float4*)(g_Vg + ((size_t)b*C + c0 + r)*N + m0 + lc);
            K7_AS(r,lc+0) = f2tf32(va.x); K7_AS(r,lc+1) = f2tf32(va.y);
            K7_AS(r,lc+2) = f2tf32(va.z); K7_AS(r,lc+3) = f2tf32(va.w);
            float4 vb = *(const float4*)(g_S + ((size_t)b*N + i0 + r)*N + m0 + lc);
            K7_BS(r,lc+0) = f2tf32(vb.x); K7_BS(r,lc+1) = f2tf32(vb.y);
            K7_BS(r,lc+2) = f2tf32(vb.z); K7_BS(r,lc+3) = f2tf32(vb.w);
        }
        __syncthreads();
        #pragma unroll
        for (int kk = 0; kk < 32; kk += 8) {
            uint32_t a0 = K7_AS(cw + gid    , kk + tig);
            uint32_t a1 = K7_AS(cw + gid + 8, kk + tig);
            uint32_t a2 = K7_AS(cw + gid    , kk + 4 + tig);
            uint32_t a3 = K7_AS(cw + gid + 8, kk + 4 + tig);
            #pragma unroll
            for (int j = 0; j < 4; j++) {
                uint32_t b0 = K7_BS(iw + 8*j + gid, kk + tig);
                uint32_t b1 = K7_BS(iw + 8*j + gid, kk + 4 + tig);
                mma_tf32(acc[j], a0, a1, a2, a3, b0, b1);
            }
        }
        __syncthreads();
    }

    // epilogue: bp tile into smem
    int clo = c0 + cw + gid;
    float bglo = 0.3f * g_bgp[b*C + clo];
    float bghi = 0.3f * g_bgp[b*C + clo + 8];
    #pragma unroll
    for (int j = 0; j < 4; j++) {
        int i = iw + 8*j + 2*tig;
        float d0 = 0.7f / g_denom[b*N + i0 + i];
        float d1 = 0.7f / g_denom[b*N + i0 + i + 1];
        K7_BP(cw + gid    , i  ) = bglo + acc[j][0] * d0;
        K7_BP(cw + gid    , i+1) = bglo + acc[j][1] * d1;
        K7_BP(cw + gid + 8, i  ) = bghi + acc[j][2] * d0;
        K7_BP(cw + gid + 8, i+1) = bghi + acc[j][3] * d1;
    }
    __syncthreads();

    // reduction: 4 threads per pixel, 16 channels each
    int px = t >> 2;
    int cs = (t & 3) * 16;
    int i = i0 + px;
    const float* qcol = q + ((size_t)b*C + c0 + cs)*N + i;
    const float* fp1  = g_FP1 + b*C + c0 + cs;
    float sdf = 0.f, sdb = 0.f, sbb = 0.f;
    #pragma unroll
    for (int k = 0; k < 16; k++) {
        float qv = qcol[(size_t)k*N];
        float bp = K7_BP(cs + k, px);
        sdf += qv * fp1[k];
        sdb += qv * bp;
        sbb += bp * bp;
    }
    sdf += __shfl_xor_sync(0xffffffffu, sdf, 1);
    sdf += __shfl_xor_sync(0xffffffffu, sdf, 2);
    sdb += __shfl_xor_sync(0xffffffffu, sdb, 1);
    sdb += __shfl_xor_sync(0xffffffffu, sdb, 2);
    sbb += __shfl_xor_sync(0xffffffffu, sbb, 1);
    sbb += __shfl_xor_sync(0xffffffffu, sbb, 2);
    if ((t & 3) == 0) {
        int cb = blockIdx.y;
        g_odf[cb][b*N + i] = sdf;
        g_odb[cb][b*N + i] = sdb;
        g_obb[cb][b*N + i] = sbb;
    }
    #undef K7_AS
    #undef K7_BS
    #undef K7_BP
}

// ---------------- K8: combine partials + write output ----------------
__global__ void k_out2(float* __restrict__ out) {
    int g = blockIdx.x * blockDim.x + threadIdx.x;
    int b = g / N, n = g % N;
    float df = 0.f, db = 0.f, bb = 0.f;
    #pragma unroll
    for (int k = 0; k < OC; k++) {
        df += g_odf[k][g];
        db += g_odb[k][g];
        bb += g_obb[k][g];
    }
    float nq = g_qn[g];
    float nb = sqrtf(bb);
    out[(b*2 + 0)*N + n] = 10.f * db / fmaxf(nq * nb, 1e-8f);
    out[(b*2 + 1)*N + n] = 10.f * df / fmaxf(nq * g_nFP1[b], 1e-8f);
}

// ---------------- launch ----------------
extern "C" void kernel_launch(void* const* d_in, const int* in_sizes, int n_in,
                              void* d_out, int out_size) {
    const float* q    = (const float*)d_in[0];
    const float* sf   = (const float*)d_in[1];
    const int*   mask = (const int*)d_in[2];
    float* out = (float*)d_out;

    k_count  <<<B, 1024>>>(mask);
    k_pool   <<<B*C/8, 256>>>(sf, mask);
    k_norms  <<<B, 512>>>();
    k_pred1  <<<dim3(B*N/256, NCHP), 256>>>(q);
    k_pred2  <<<B*N/256, 256>>>();
    k_weights<<<dim3(2, B), 1024>>>();
    k_gfg    <<<B*C, 128>>>(q);
    k_fp1    <<<B, 512>>>();
    k5_mma   <<<dim3(N/64, N/64, B), 256>>>(q);
    k7_mma   <<<dim3(N/64, C/64, B), 256>>>(q);
    k_out2   <<<B*N/256, 256>>>(out);
}